// round 9
// baseline (speedup 1.0000x reference)
#include <cuda_runtime.h>
#include <math.h>
#include <float.h>

// Problem constants: B=8, Z=4, X=32, Y=32, N=4096
#define NPTS   4096
#define NB     8
#define THREADS 512
#define NWARP  (THREADS / 32)
#define NITER  (NPTS / THREADS)   // 8
#define MAXK   32
#define CUT2   4.0f               // sqrt(ss) < 2  <=>  ss < 4 (exact)

// Dynamic smem: two float4 arrays of NPTS
#define SMEM_BYTES (2 * NPTS * 16)

__device__ __forceinline__ float row_angle(float ax, float ay, float az,
                                           float bx, float by, float bz) {
    float na = sqrtf(ax * ax + ay * ay + az * az);
    float nb = sqrtf(bx * bx + by * by + bz * bz);
    float c = (ax * bx + ay * by + az * bz) / (na * nb);
    c = fminf(1.0f, fmaxf(-1.0f, c));
    return (acosf(c) / 3.14159265358979323846f) * 180.0f;
}

__global__ __launch_bounds__(THREADS, 1)
void mol_kernel(const float* __restrict__ pred,
                const float* __restrict__ targ,
                float* __restrict__ out) {
    extern __shared__ float sm[];
    float4* sP4 = (float4*)sm;          // [NPTS] (x,y,z norm, conf | -FLT_MAX)
    float4* sT4 = sP4 + NPTS;           // [NPTS] (tx real | 1e30 sentinel, ty, tz, -)
    float*  smf = sm;                   // scalar view for conf (.w) kill-stores

    __shared__ float wv[NWARP];
    __shared__ int   wiA[NWARP];
    __shared__ int   sK, sSel, sNTG;
    __shared__ float selp[3];
    __shared__ int   kId[MAXK];
    __shared__ float kRX[MAXK], kRY[MAXK], kRZ[MAXK];
    __shared__ int   sMatch[MAXK], sHit[MAXK];
    __shared__ float sAngA[MAXK];

    const int tid = threadIdx.x;
    const int lane = tid & 31;
    const int warp = tid >> 5;
    const int b = blockIdx.x;
    const float* P = pred + (long long)b * NPTS * 10;
    const float* T = targ + (long long)b * NPTS * 10;

    // ---- Phase 1: vectorized, fully-unrolled load (high MLP) — R8 verbatim ----
    int cnt = 0;
    #pragma unroll
    for (int j = 0; j < NITER; j++) {
        int n = tid + j * THREADS;
        const float* p = P + n * 10;
        const float* t = T + n * 10;
        // 40-byte pitch is 8-byte aligned for every n -> float2 loads legal
        float2 p01 = *(const float2*)p;
        float2 p23 = *(const float2*)(p + 2);
        float2 t01 = *(const float2*)t;
        float2 t23 = *(const float2*)(t + 2);
        float z = (float)(n >> 10), x = (float)((n >> 5) & 31), y = (float)(n & 31);
        // sigmoid(c) > 0.5 <=> c > 0 (exact); /4, /32 exact pow2 mults
        sP4[n] = make_float4((p01.y + z) * 0.25f,
                             (p23.x + x) * 0.03125f,
                             (p23.y + y) * 0.03125f,
                             (p01.x > 0.0f) ? p01.x : -FLT_MAX);
        bool act = t01.x > 0.5f;
        cnt += act ? 1 : 0;
        // real coords; inactive -> x sentinel makes every distance test fail
        sT4[n] = make_float4(act ? ((t01.y + z) * 0.25f) * 25.0f : 1e30f,
                             ((t23.x + x) * 0.03125f) * 25.0f,
                             ((t23.y + y) * 0.03125f) * 4.0f,
                             0.0f);
    }
    // fold target count into load phase
    #pragma unroll
    for (int o = 16; o; o >>= 1) cnt += __shfl_down_sync(0xffffffffu, cnt, o);
    if (lane == 0) wiA[warp] = cnt;
    if (tid == 0) {
        sK = 0;
        selp[0] = 1e30f; selp[1] = 1e30f; selp[2] = 1e30f;  // round 0: nothing suppressed
    }
    __syncthreads();
    if (tid == 0) {
        int s = 0;
        for (int w = 0; w < NWARP; w++) s += wiA[w];
        sNTG = s;
    }
    __syncthreads();

    // ---- Phase 2: greedy NMS; suppression of previous pick fused into argmax ----
    for (;;) {
        float c0 = selp[0], c1 = selp[1], c2 = selp[2];
        float bv = -FLT_MAX;
        int bi = 0x7fffffff;
        #pragma unroll
        for (int j = 0; j < NITER; j++) {
            int n = tid + j * THREADS;
            float4 q = sP4[n];
            float v = q.w;
            if (v != -FLT_MAX) {
                float d0 = q.x - c0, d1 = q.y - c1, d2 = q.z - c2;
                float ss = (d0 * d0 + d1 * d1) + d2 * d2;
                if (ss < CUT2) { smf[4 * n + 3] = -FLT_MAX; v = -FLT_MAX; }
            }
            if (v > bv) { bv = v; bi = n; }   // ascending n keeps lowest idx on tie
        }
        #pragma unroll
        for (int o = 16; o; o >>= 1) {
            float v2 = __shfl_down_sync(0xffffffffu, bv, o);
            int i2 = __shfl_down_sync(0xffffffffu, bi, o);
            if (v2 > bv || (v2 == bv && i2 < bi)) { bv = v2; bi = i2; }
        }
        if (lane == 0) { wv[warp] = bv; wiA[warp] = bi; }
        __syncthreads();
        if (warp == 0) {
            float v = (lane < NWARP) ? wv[lane] : -FLT_MAX;
            int i = (lane < NWARP) ? wiA[lane] : 0x7fffffff;
            #pragma unroll
            for (int o = 8; o; o >>= 1) {
                float v2 = __shfl_down_sync(0xffffffffu, v, o);
                int i2 = __shfl_down_sync(0xffffffffu, i, o);
                if (v2 > v || (v2 == v && i2 < i)) { v = v2; i = i2; }
            }
            if (lane == 0) {
                if (v == -FLT_MAX || sK >= MAXK) {
                    sSel = -1;
                } else {
                    int K = sK;
                    float4 q = sP4[i];
                    kId[K] = i;
                    kRX[K] = q.x * 25.0f; kRY[K] = q.y * 25.0f; kRZ[K] = q.z * 4.0f;
                    selp[0] = q.x; selp[1] = q.y; selp[2] = q.z;
                    sK = K + 1;
                    sSel = i;
                }
            }
        }
        __syncthreads();
        if (sSel < 0) break;
    }

    // ---- Phase 3: warp-parallel matching — warp w handles kept points w, w+16 ----
    const int K = sK;
    for (int k = warp; k < K; k += NWARP) {
        float qx = kRX[k], qy = kRY[k], qz = kRZ[k];
        int best = 0x7fffffff;
        #pragma unroll 4
        for (int e = lane; e < NPTS; e += 32) {
            float4 q = sT4[e];
            float d0 = q.x - qx, d1 = q.y - qy, d2 = q.z - qz;
            float ss = (d0 * d0 + d1 * d1) + d2 * d2;
            if (ss < CUT2 && e < best) best = e;   // sentinel 1e30 auto-fails
        }
        #pragma unroll
        for (int o = 16; o; o >>= 1) {
            int v2 = __shfl_down_sync(0xffffffffu, best, o);
            if (v2 < best) best = v2;
        }
        if (lane == 0) sMatch[k] = best;
    }
    __syncthreads();

    // ---- Phase 4: K parallel angle computations (global reads, L2-hot) ----
    if (tid < K) {
        int mt = sMatch[tid];
        if (mt != 0x7fffffff) {
            const float* p = P + (long long)kId[tid] * 10 + 4;
            const float* t = T + (long long)mt * 10 + 4;
            float2 pa2 = *(const float2*)p;        // offsets 4..9 are 8B aligned
            float2 pb2 = *(const float2*)(p + 2);
            float2 pc2 = *(const float2*)(p + 4);
            float2 ta2 = *(const float2*)t;
            float2 tb2 = *(const float2*)(t + 2);
            float2 tc2 = *(const float2*)(t + 4);
            float ax = pa2.x, ay = pa2.y, az = pb2.x;
            float bx = pb2.y, by = pc2.x, bz = pc2.y;
            float cx = ay * bz - az * by;
            float cy = az * bx - ax * bz;
            float cz = ax * by - ay * bx;
            float tax = ta2.x, tay = ta2.y, taz = tb2.x;
            float tbx = tb2.y, tby = tc2.x, tbz = tc2.y;
            float tcx = tay * tbz - taz * tby;
            float tcy = taz * tbx - tax * tbz;
            float tcz = tax * tby - tay * tbx;
            sAngA[tid] = row_angle(ax, ay, az, tax, tay, taz)
                       + row_angle(bx, by, bz, tbx, tby, tbz)
                       + row_angle(cx, cy, cz, tcx, tcy, tcz);
            sHit[tid] = 1;
        } else {
            sAngA[tid] = 0.0f;
            sHit[tid] = 0;
        }
    }
    __syncthreads();

    // ---- Phase 5: deterministic epilogue ----
    if (tid == 0) {
        int tp = 0;
        float ang = 0.0f;
        for (int k = 0; k < K; k++) { tp += sHit[k]; ang += sAngA[k]; }
        float tpf = (float)tp;
        out[b * 3 + 0] = tpf;
        out[b * 3 + 1] = (float)K - tpf;
        out[b * 3 + 2] = (float)sNTG - tpf;
        out[3 * NB + b] = (tp > 0) ? (ang / (3.0f * tpf)) : 0.0f;
    }
}

extern "C" void kernel_launch(void* const* d_in, const int* in_sizes, int n_in,
                              void* d_out, int out_size) {
    const float* pred = (const float*)d_in[0];
    const float* targ = (const float*)d_in[1];
    float* out = (float*)d_out;
    cudaFuncSetAttribute(mol_kernel, cudaFuncAttributeMaxDynamicSharedMemorySize,
                         SMEM_BYTES);
    mol_kernel<<<NB, THREADS, SMEM_BYTES>>>(pred, targ, out);
}